// round 13
// baseline (speedup 1.0000x reference)
#include <cuda_runtime.h>
#include <cuda_bf16.h>
#include <cuda_fp16.h>
#include <cstdint>

#define N_PTS 100000
#define D 128
#define NSM 148
#define SKPB 272               // 16b row stride in bytes (136 elems)
#define TILE_B 34816           // 128 * 272
#define BUF_SZ (2 * TILE_B)
#define TILES_A 782
#define TILES_BK 6250          // 800000 / 128

// kernel A smem layout (bf16 split-3)
#define SA_WH   139264
#define SA_WL   (SA_WH + TILE_B)
#define SA_TOT  208896

// kernel B smem layout (TILE_M=128, plain fp16, reg-cached B, 256 thr)
#define B_WH    69632                  // after 2 A buffers
#define B_W1S   104448                 // 3*128 floats
#define B_B1    105984                 // 128 floats
#define B_IDX   106496                 // 4 * 512
#define B_XYZ   108544                 // 4 * 1536
#define B_B2    114688                 // 512
#define B_TOT   115200

__device__ __half g_y[(size_t)N_PTS * D];

// ---------------- helpers ----------------
__device__ __forceinline__ uint32_t smem_u32(const void* p) {
    uint32_t a;
    asm("{ .reg .u64 t; cvta.to.shared.u64 t, %1; cvt.u32.u64 %0, t; }"
        : "=r"(a) : "l"(p));
    return a;
}
__device__ __forceinline__ uint32_t cvt_bf16x2(float hi, float lo) {
    uint32_t r;
    asm("cvt.rn.bf16x2.f32 %0, %1, %2;" : "=r"(r) : "f"(hi), "f"(lo));
    return r;
}
__device__ __forceinline__ uint32_t cvt_f16x2(float hi, float lo) {
    uint32_t r;
    asm("cvt.rn.f16x2.f32 %0, %1, %2;" : "=r"(r) : "f"(hi), "f"(lo));
    return r;
}
__device__ __forceinline__ void cp16(uint32_t dst, const void* src) {
    asm volatile("cp.async.cg.shared.global [%0], [%1], 16;"
                 :: "r"(dst), "l"(src) : "memory");
}
__device__ __forceinline__ void cp_commit() {
    asm volatile("cp.async.commit_group;" ::: "memory");
}
__device__ __forceinline__ void cp_wait0() {
    asm volatile("cp.async.wait_group 0;" ::: "memory");
}
__device__ __forceinline__ void ldsm_x4(uint32_t addr, uint32_t* r) {
    asm volatile("ldmatrix.sync.aligned.m8n8.x4.shared.b16 {%0,%1,%2,%3}, [%4];"
                 : "=r"(r[0]), "=r"(r[1]), "=r"(r[2]), "=r"(r[3]) : "r"(addr));
}
__device__ __forceinline__ void ldsm_x2(uint32_t addr, uint32_t* r) {
    asm volatile("ldmatrix.sync.aligned.m8n8.x2.shared.b16 {%0,%1}, [%2];"
                 : "=r"(r[0]), "=r"(r[1]) : "r"(addr));
}
__device__ __forceinline__ void mma_bf16(float* d, const uint32_t* a, const uint32_t* b) {
    asm volatile(
        "mma.sync.aligned.m16n8k16.row.col.f32.bf16.bf16.f32 "
        "{%0,%1,%2,%3}, {%4,%5,%6,%7}, {%8,%9}, {%0,%1,%2,%3};"
        : "+f"(d[0]), "+f"(d[1]), "+f"(d[2]), "+f"(d[3])
        : "r"(a[0]), "r"(a[1]), "r"(a[2]), "r"(a[3]), "r"(b[0]), "r"(b[1]));
}
__device__ __forceinline__ void mma_f16(float* d, const uint32_t* a, const uint32_t* b) {
    asm volatile(
        "mma.sync.aligned.m16n8k16.row.col.f32.f16.f16.f32 "
        "{%0,%1,%2,%3}, {%4,%5,%6,%7}, {%8,%9}, {%0,%1,%2,%3};"
        : "+f"(d[0]), "+f"(d[1]), "+f"(d[2]), "+f"(d[3])
        : "r"(a[0]), "r"(a[1]), "r"(a[2]), "r"(a[3]), "r"(b[0]), "r"(b[1]));
}
__device__ __forceinline__ void split4(float4 v, uint2& hi, uint2& lo) {
    uint32_t h01 = cvt_bf16x2(v.y, v.x);
    uint32_t h23 = cvt_bf16x2(v.w, v.z);
    float rx = v.x - __uint_as_float(h01 << 16);
    float ry = v.y - __uint_as_float(h01 & 0xffff0000u);
    float rz = v.z - __uint_as_float(h23 << 16);
    float rw = v.w - __uint_as_float(h23 & 0xffff0000u);
    hi = make_uint2(h01, h23);
    lo = make_uint2(cvt_bf16x2(ry, rx), cvt_bf16x2(rw, rz));
}
__device__ __forceinline__ float4 leaky4(float4 v) {
    v.x = v.x > 0.f ? v.x : 0.01f * v.x;
    v.y = v.y > 0.f ? v.y : 0.01f * v.y;
    v.z = v.z > 0.f ? v.z : 0.01f * v.z;
    v.w = v.w > 0.f ? v.w : 0.01f * v.w;
    return v;
}

// =====================================================================
// Kernel A (persistent, pipelined, 256 thr, bf16 split-3), y stored fp16
// =====================================================================
__device__ __forceinline__ void build_w_bf16(char* smc, const float* W, int tid) {
    for (int i = tid; i < 128 * 128; i += 256) {
        int k = i >> 7, n = i & 127;
        float v = W[i];
        __nv_bfloat16 hb = __float2bfloat16(v);
        *(__nv_bfloat16*)(smc + SA_WH + n * SKPB + k * 2) = hb;
        *(__nv_bfloat16*)(smc + SA_WL + n * SKPB + k * 2) =
            __float2bfloat16(v - __bfloat162float(hb));
    }
}

__device__ __forceinline__ void mma_kstep64(uint32_t abuf, uint32_t aRowOff,
                                            uint32_t bRowW, int ks, float d[2][8][4]) {
    const uint32_t kb = ks * 32;
    uint32_t ah[2][4], al[2][4];
#pragma unroll
    for (int mt = 0; mt < 2; mt++) {
        uint32_t off = abuf + aRowOff + (uint32_t)mt * 16 * SKPB + kb;
        ldsm_x4(off, ah[mt]);
        ldsm_x4(off + TILE_B, al[mt]);
    }
    uint32_t bh[8][2], bl[8][2];
#pragma unroll
    for (int nt = 0; nt < 8; nt++) {
        uint32_t off = bRowW + (uint32_t)nt * 8 * SKPB + kb;
        ldsm_x2(off, bh[nt]);
        ldsm_x2(off + TILE_B, bl[nt]);
    }
#pragma unroll
    for (int mt = 0; mt < 2; mt++)
#pragma unroll
        for (int nt = 0; nt < 8; nt++) {
            mma_bf16(d[mt][nt], ah[mt], bh[nt]);
            mma_bf16(d[mt][nt], al[mt], bh[nt]);
            mma_bf16(d[mt][nt], ah[mt], bl[nt]);
        }
}

__global__ void __launch_bounds__(256, 1)
gemm1_kernel(const float* __restrict__ x, const float* __restrict__ W1) {
    extern __shared__ char smc[];
    const uint32_t sb = smem_u32(smc);
    const int tid = threadIdx.x, w = tid >> 5, lane = tid & 31;
    const int w16 = w * 16, c0 = lane * 4;
    const int m0 = (w & 3) * 32, n0 = (w >> 2) * 64;
    const uint32_t aRowOff = (uint32_t)(m0 + (lane & 15)) * SKPB + (lane >> 4) * 16;
    const uint32_t bRowW = sb + SA_WH + (uint32_t)(n0 + (lane & 7)) * SKPB +
                           ((lane >> 3) & 1) * 16;
    char* gyc = (char*)g_y;

    build_w_bf16(smc, W1, tid);

    const int t0 = blockIdx.x;
    float4 xreg[16];
#pragma unroll
    for (int rr = 0; rr < 16; rr++) {
        int row = t0 * 128 + w16 + rr;
        xreg[rr] = *(const float4*)(x + (size_t)(row < N_PTS ? row : 0) * D + c0);
    }
#pragma unroll
    for (int rr = 0; rr < 16; rr++) {
        uint2 hi, lo; split4(xreg[rr], hi, lo);
        uint32_t off = (uint32_t)(w16 + rr) * SKPB + c0 * 2;
        *(uint2*)(smc + off) = hi;
        *(uint2*)(smc + TILE_B + off) = lo;
    }
    {
        int tn = t0 + NSM;
#pragma unroll
        for (int rr = 0; rr < 16; rr++) {
            int row = tn * 128 + w16 + rr;
            xreg[rr] = *(const float4*)(x + (size_t)(row < N_PTS ? row : 0) * D + c0);
        }
    }
    __syncthreads();

    int p = 0;
    for (int t = t0; t < TILES_A; t += NSM, p ^= 1) {
        const uint32_t abuf = sb + p * BUF_SZ;
        char* cb = smc + (p ^ 1) * BUF_SZ;
        const int t2 = t + 2 * NSM;

        float d[2][8][4];
#pragma unroll
        for (int mt = 0; mt < 2; mt++)
#pragma unroll
            for (int nt = 0; nt < 8; nt++)
#pragma unroll
                for (int j = 0; j < 4; j++) d[mt][nt][j] = 0.f;

#pragma unroll
        for (int ks = 0; ks < 8; ks++) {
            mma_kstep64(abuf, aRowOff, bRowW, ks, d);
            const int rr = 2 * ks;
#pragma unroll
            for (int q = 0; q < 2; q++) {
                uint2 hi, lo; split4(xreg[rr + q], hi, lo);
                uint32_t off = (uint32_t)(w16 + rr + q) * SKPB + c0 * 2;
                *(uint2*)(cb + off) = hi;
                *(uint2*)(cb + TILE_B + off) = lo;
                int row = t2 * 128 + w16 + rr + q;
                xreg[rr + q] =
                    *(const float4*)(x + (size_t)(row < N_PTS ? row : 0) * D + c0);
            }
        }

        const int g = lane >> 2, tt2 = 2 * (lane & 3);
        const int base = t * 128;
#pragma unroll
        for (int mt = 0; mt < 2; mt++) {
            int row0 = base + m0 + mt * 16 + g;
#pragma unroll
            for (int nt = 0; nt < 8; nt++) {
                int col = n0 + nt * 8 + tt2;
                if (row0 < N_PTS)
                    *(uint32_t*)(gyc + ((size_t)row0 * D + col) * 2) =
                        cvt_f16x2(d[mt][nt][1], d[mt][nt][0]);
                if (row0 + 8 < N_PTS)
                    *(uint32_t*)(gyc + ((size_t)(row0 + 8) * D + col) * 2) =
                        cvt_f16x2(d[mt][nt][3], d[mt][nt][2]);
            }
        }
        __syncthreads();
    }
}

// =====================================================================
// Kernel B: 256 thr, 8 warps m64xn32, fp16, B fragments cached in regs
// =====================================================================
__device__ __forceinline__ void build_w_f16(char* smc, const float* W, int tid) {
    for (int i = tid; i < 128 * 128; i += 256) {
        int k = i >> 7, n = i & 127;
        *(__half*)(smc + B_WH + n * SKPB + k * 2) = __float2half_rn(W[i]);
    }
}
__device__ __forceinline__ void prefetch_ix(uint32_t sb, const int* idx,
                                            const float* xyz, int tile, int slot,
                                            int tid) {
    if (tile >= TILES_BK) tile = TILES_BK - 1;
    if (tid < 32)
        cp16(sb + B_IDX + slot * 512 + tid * 16, idx + (size_t)tile * 128 + tid * 4);
    else if (tid < 128)
        cp16(sb + B_XYZ + slot * 1536 + (tid - 32) * 16,
             xyz + (size_t)tile * 384 + (tid - 32) * 4);
}

// convert one gathered fp16 y row -> act fp16 row in dst (params from smem)
__device__ __forceinline__ void convert_row(char* dst, const float* w1s,
                                            const float* b1s, const float* xz,
                                            int r, int c0, uint2 yv) {
    float2 f01 = __half22float2(*(__half2*)&yv.x);
    float2 f23 = __half22float2(*(__half2*)&yv.y);
    float4 v = make_float4(f01.x, f01.y, f23.x, f23.y);
    float px = xz[r * 3], py = xz[r * 3 + 1], pz = xz[r * 3 + 2];
    float4 wA = *(const float4*)(w1s + c0);
    float4 wB = *(const float4*)(w1s + 128 + c0);
    float4 wC = *(const float4*)(w1s + 256 + c0);
    float4 bb = *(const float4*)(b1s + c0);
    v.x += px * wA.x + py * wB.x + pz * wC.x + bb.x;
    v.y += px * wA.y + py * wB.y + pz * wC.y + bb.y;
    v.z += px * wA.z + py * wB.z + pz * wC.z + bb.z;
    v.w += px * wA.w + py * wB.w + pz * wC.w + bb.w;
    v = leaky4(v);
    *(uint2*)(dst + (uint32_t)r * SKPB + c0 * 2) =
        make_uint2(cvt_f16x2(v.y, v.x), cvt_f16x2(v.w, v.z));
}

__global__ void __launch_bounds__(256, 1)
gemm2_pool_kernel(const int*   __restrict__ idx,
                  const float* __restrict__ xyz,
                  const float* __restrict__ W1,
                  const float* __restrict__ b1,
                  const float* __restrict__ W2,
                  const float* __restrict__ b2,
                  float* __restrict__ out) {
    extern __shared__ char smc[];
    const uint32_t sb = smem_u32(smc);
    const int tid = threadIdx.x, w = tid >> 5, lane = tid & 31;
    const int w16 = w * 16, c0 = lane * 4;
    const int m0 = (w >> 2) * 64, n0 = (w & 3) * 32;
    const uint32_t aRowOff = (uint32_t)(m0 + (lane & 15)) * SKPB + (lane >> 4) * 16;
    const uint32_t bRow4 = sb + B_WH +
        (uint32_t)(n0 + (lane & 7) + ((lane >> 4) & 1) * 8) * SKPB +
        ((lane >> 3) & 1) * 16;
    const char* gyc = (const char*)g_y;
    const uint32_t lane8 = lane * 8;
    float* w1s = (float*)(smc + B_W1S);
    float* b1s = (float*)(smc + B_B1);
    float* b2s = (float*)(smc + B_B2);

    build_w_f16(smc, W2, tid);
    if (tid < 128) { b1s[tid] = b1[tid]; b2s[tid] = b2[tid]; }
    for (int i = tid; i < 3 * 128; i += 256) w1s[i] = W1[128 * 128 + i];

    const int t0 = blockIdx.x;
    prefetch_ix(sb, idx, xyz, t0, 0, tid);
    prefetch_ix(sb, idx, xyz, t0 + NSM, 1, tid);
    prefetch_ix(sb, idx, xyz, t0 + 2 * NSM, 2, tid);
    cp_commit();
    cp_wait0();
    __syncthreads();

    // cache all B fragments in registers (tile-invariant W2): 64 regs
    uint32_t breg[8][8];
#pragma unroll
    for (int ks = 0; ks < 8; ks++) {
        ldsm_x4(bRow4 + ks * 32, breg[ks]);
        ldsm_x4(bRow4 + 16 * SKPB + ks * 32, breg[ks] + 4);
    }

    // prologue: gather+convert tile t0 -> buf0 (16 rows per warp)
    {
        const int* idxs = (const int*)(smc + B_IDX);
        const float* xz = (const float*)(smc + B_XYZ);
#pragma unroll 4
        for (int rr = 0; rr < 16; rr++) {
            int r = w16 + rr;
            int id = idxs[r];
            uint2 yv = *(const uint2*)(gyc + (size_t)id * 256 + lane8);
            convert_row(smc, w1s, b1s, xz, r, c0, yv);
        }
    }
    __syncthreads();

    uint2 yring[4];
    int p = 0, i = 0;
    for (int t = t0; t < TILES_BK; t += NSM, i++, p ^= 1) {
        const int* idx1 = (const int*)(smc + B_IDX + ((i + 1) & 3) * 512);
        const float* xz1 = (const float*)(smc + B_XYZ + ((i + 1) & 3) * 1536);
        const uint32_t abuf = sb + p * TILE_B;
        char* cb = smc + (p ^ 1) * TILE_B;

        float d[4][4][4];
#pragma unroll
        for (int mt = 0; mt < 4; mt++)
#pragma unroll
            for (int nt = 0; nt < 4; nt++)
#pragma unroll
                for (int j = 0; j < 4; j++) d[mt][nt][j] = 0.f;

        // preload A frags for ks=0
        uint32_t acur[4][4], anxt[4][4];
#pragma unroll
        for (int mt = 0; mt < 4; mt++)
            ldsm_x4(abuf + aRowOff + (uint32_t)mt * 16 * SKPB, acur[mt]);

#pragma unroll
        for (int ks = 0; ks < 8; ks++) {
            // prefetch A for next k-step
            if (ks < 7) {
                const uint32_t kb = (ks + 1) * 32;
#pragma unroll
                for (int mt = 0; mt < 4; mt++)
                    ldsm_x4(abuf + aRowOff + (uint32_t)mt * 16 * SKPB + kb,
                            anxt[mt]);
            }
            // 16 HMMA (B from registers)
#pragma unroll
            for (int mt = 0; mt < 4; mt++)
#pragma unroll
                for (int nt = 0; nt < 4; nt++)
                    mma_f16(d[mt][nt], acur[mt],
                            &breg[ks][(nt >> 1) * 4 + (nt & 1) * 2]);

            // convert rows gathered 2 steps ago BEFORE regathering same slots
            if (ks >= 2) {
                const int rr = 2 * (ks - 2);
#pragma unroll
                for (int q = 0; q < 2; q++)
                    convert_row(cb, w1s, b1s, xz1, w16 + rr + q, c0,
                                yring[(rr + q) & 3]);
            }
            const int rg = 2 * ks;
#pragma unroll
            for (int q = 0; q < 2; q++) {
                int id = idx1[w16 + rg + q];
                yring[(rg + q) & 3] =
                    *(const uint2*)(gyc + (size_t)id * 256 + lane8);
            }
#pragma unroll
            for (int mt = 0; mt < 4; mt++)
#pragma unroll
                for (int j = 0; j < 4; j++) acur[mt][j] = anxt[mt][j];
        }
        // tail converts: rows 12..15
#pragma unroll
        for (int rr = 12; rr < 16; rr++)
            convert_row(cb, w1s, b1s, xz1, w16 + rr, c0, yring[rr & 3]);

        cp_wait0();
        prefetch_ix(sb, idx, xyz, t + 3 * NSM, (i + 3) & 3, tid);
        cp_commit();

        // epilogue: maxpool over 8 rows, +b2, store
        const long rowbase = (long)t * 128;
        const int tt2 = 2 * (lane & 3);
#pragma unroll
        for (int mt = 0; mt < 4; mt++) {
            long p0 = (rowbase + m0 + mt * 16) >> 3;
            long p1 = p0 + 1;
#pragma unroll
            for (int nt = 0; nt < 4; nt++) {
                float v0 = d[mt][nt][0], v1 = d[mt][nt][1];
                float v2 = d[mt][nt][2], v3 = d[mt][nt][3];
#pragma unroll
                for (int s = 4; s < 32; s <<= 1) {
                    v0 = fmaxf(v0, __shfl_xor_sync(0xffffffffu, v0, s));
                    v1 = fmaxf(v1, __shfl_xor_sync(0xffffffffu, v1, s));
                    v2 = fmaxf(v2, __shfl_xor_sync(0xffffffffu, v2, s));
                    v3 = fmaxf(v3, __shfl_xor_sync(0xffffffffu, v3, s));
                }
                if (lane < 4) {
                    int col = n0 + nt * 8 + tt2;
                    float bx = b2s[col], by = b2s[col + 1];
                    *(float2*)(out + (size_t)p0 * D + col) = make_float2(v0 + bx, v1 + by);
                    *(float2*)(out + (size_t)p1 * D + col) = make_float2(v2 + bx, v3 + by);
                }
            }
        }
        __syncthreads();
    }
}

// =====================================================================
extern "C" void kernel_launch(void* const* d_in, const int* in_sizes, int n_in,
                              void* d_out, int out_size) {
    const float* x   = (const float*)d_in[0];
    const int*   idx = (const int*)d_in[1];
    const float* xyz = (const float*)d_in[2];
    const float* W1  = (const float*)d_in[3];
    const float* b1  = (const float*)d_in[4];
    const float* W2  = (const float*)d_in[5];
    const float* b2  = (const float*)d_in[6];
    float* out = (float*)d_out;

    cudaFuncSetAttribute(gemm1_kernel,
                         cudaFuncAttributeMaxDynamicSharedMemorySize, SA_TOT);
    cudaFuncSetAttribute(gemm2_pool_kernel,
                         cudaFuncAttributeMaxDynamicSharedMemorySize, B_TOT);

    gemm1_kernel<<<NSM, 256, SA_TOT>>>(x, W1);
    gemm2_pool_kernel<<<NSM, 256, B_TOT>>>(idx, xyz, W1, b1, W2, b2, out);
}

// round 14
// speedup vs baseline: 1.3529x; 1.3529x over previous
#include <cuda_runtime.h>
#include <cuda_bf16.h>
#include <cuda_fp16.h>
#include <cstdint>

#define N_PTS 100000
#define D 128
#define NSM 148
#define SKPB 272               // 16b row stride in bytes (136 elems)
#define TILE_B 34816           // 128 * 272
#define BUF_SZ (2 * TILE_B)
#define TILES_A 782
#define TILES_BK 6250          // 800000 / 128

// kernel A smem layout (bf16 split-3)
#define SA_WH   139264
#define SA_WL   (SA_WH + TILE_B)
#define SA_TOT  208896

// kernel B smem layout (R10: TILE_M=128, plain fp16, 512 thr)
#define B_WH    69632                  // after 2 single-image A buffers
#define B_IDX   104448                 // 4 * 512
#define B_XYZ   106496                 // 4 * 1536
#define B_B2    112640                 // 512
#define B_TOT   113152

__device__ __half g_y[(size_t)N_PTS * D];

// ---------------- helpers ----------------
__device__ __forceinline__ uint32_t smem_u32(const void* p) {
    uint32_t a;
    asm("{ .reg .u64 t; cvta.to.shared.u64 t, %1; cvt.u32.u64 %0, t; }"
        : "=r"(a) : "l"(p));
    return a;
}
__device__ __forceinline__ uint32_t cvt_bf16x2(float hi, float lo) {
    uint32_t r;
    asm("cvt.rn.bf16x2.f32 %0, %1, %2;" : "=r"(r) : "f"(hi), "f"(lo));
    return r;
}
__device__ __forceinline__ uint32_t cvt_f16x2(float hi, float lo) {
    uint32_t r;
    asm("cvt.rn.f16x2.f32 %0, %1, %2;" : "=r"(r) : "f"(hi), "f"(lo));
    return r;
}
__device__ __forceinline__ void cp16(uint32_t dst, const void* src) {
    asm volatile("cp.async.cg.shared.global [%0], [%1], 16;"
                 :: "r"(dst), "l"(src) : "memory");
}
__device__ __forceinline__ void cp_commit() {
    asm volatile("cp.async.commit_group;" ::: "memory");
}
__device__ __forceinline__ void cp_wait0() {
    asm volatile("cp.async.wait_group 0;" ::: "memory");
}
__device__ __forceinline__ void ldsm_x4(uint32_t addr, uint32_t* r) {
    asm volatile("ldmatrix.sync.aligned.m8n8.x4.shared.b16 {%0,%1,%2,%3}, [%4];"
                 : "=r"(r[0]), "=r"(r[1]), "=r"(r[2]), "=r"(r[3]) : "r"(addr));
}
__device__ __forceinline__ void ldsm_x2(uint32_t addr, uint32_t* r) {
    asm volatile("ldmatrix.sync.aligned.m8n8.x2.shared.b16 {%0,%1}, [%2];"
                 : "=r"(r[0]), "=r"(r[1]) : "r"(addr));
}
__device__ __forceinline__ void mma_bf16(float* d, const uint32_t* a, const uint32_t* b) {
    asm volatile(
        "mma.sync.aligned.m16n8k16.row.col.f32.bf16.bf16.f32 "
        "{%0,%1,%2,%3}, {%4,%5,%6,%7}, {%8,%9}, {%0,%1,%2,%3};"
        : "+f"(d[0]), "+f"(d[1]), "+f"(d[2]), "+f"(d[3])
        : "r"(a[0]), "r"(a[1]), "r"(a[2]), "r"(a[3]), "r"(b[0]), "r"(b[1]));
}
__device__ __forceinline__ void mma_f16(float* d, const uint32_t* a, const uint32_t* b) {
    asm volatile(
        "mma.sync.aligned.m16n8k16.row.col.f32.f16.f16.f32 "
        "{%0,%1,%2,%3}, {%4,%5,%6,%7}, {%8,%9}, {%0,%1,%2,%3};"
        : "+f"(d[0]), "+f"(d[1]), "+f"(d[2]), "+f"(d[3])
        : "r"(a[0]), "r"(a[1]), "r"(a[2]), "r"(a[3]), "r"(b[0]), "r"(b[1]));
}
__device__ __forceinline__ void split4(float4 v, uint2& hi, uint2& lo) {
    uint32_t h01 = cvt_bf16x2(v.y, v.x);
    uint32_t h23 = cvt_bf16x2(v.w, v.z);
    float rx = v.x - __uint_as_float(h01 << 16);
    float ry = v.y - __uint_as_float(h01 & 0xffff0000u);
    float rz = v.z - __uint_as_float(h23 << 16);
    float rw = v.w - __uint_as_float(h23 & 0xffff0000u);
    hi = make_uint2(h01, h23);
    lo = make_uint2(cvt_bf16x2(ry, rx), cvt_bf16x2(rw, rz));
}
__device__ __forceinline__ float4 leaky4(float4 v) {
    v.x = v.x > 0.f ? v.x : 0.01f * v.x;
    v.y = v.y > 0.f ? v.y : 0.01f * v.y;
    v.z = v.z > 0.f ? v.z : 0.01f * v.z;
    v.w = v.w > 0.f ? v.w : 0.01f * v.w;
    return v;
}

// =====================================================================
// Kernel A (persistent, pipelined, 256 thr, bf16 split-3), y stored fp16
// =====================================================================
__device__ __forceinline__ void build_w_bf16(char* smc, const float* W, int tid) {
    for (int i = tid; i < 128 * 128; i += 256) {
        int k = i >> 7, n = i & 127;
        float v = W[i];
        __nv_bfloat16 hb = __float2bfloat16(v);
        *(__nv_bfloat16*)(smc + SA_WH + n * SKPB + k * 2) = hb;
        *(__nv_bfloat16*)(smc + SA_WL + n * SKPB + k * 2) =
            __float2bfloat16(v - __bfloat162float(hb));
    }
}

__device__ __forceinline__ void mma_kstep64(uint32_t abuf, uint32_t aRowOff,
                                            uint32_t bRowW, int ks, float d[2][8][4]) {
    const uint32_t kb = ks * 32;
    uint32_t ah[2][4], al[2][4];
#pragma unroll
    for (int mt = 0; mt < 2; mt++) {
        uint32_t off = abuf + aRowOff + (uint32_t)mt * 16 * SKPB + kb;
        ldsm_x4(off, ah[mt]);
        ldsm_x4(off + TILE_B, al[mt]);
    }
    uint32_t bh[8][2], bl[8][2];
#pragma unroll
    for (int nt = 0; nt < 8; nt++) {
        uint32_t off = bRowW + (uint32_t)nt * 8 * SKPB + kb;
        ldsm_x2(off, bh[nt]);
        ldsm_x2(off + TILE_B, bl[nt]);
    }
#pragma unroll
    for (int mt = 0; mt < 2; mt++)
#pragma unroll
        for (int nt = 0; nt < 8; nt++) {
            mma_bf16(d[mt][nt], ah[mt], bh[nt]);
            mma_bf16(d[mt][nt], al[mt], bh[nt]);
            mma_bf16(d[mt][nt], ah[mt], bl[nt]);
        }
}

__global__ void __launch_bounds__(256, 1)
gemm1_kernel(const float* __restrict__ x, const float* __restrict__ W1) {
    extern __shared__ char smc[];
    const uint32_t sb = smem_u32(smc);
    const int tid = threadIdx.x, w = tid >> 5, lane = tid & 31;
    const int w16 = w * 16, c0 = lane * 4;
    const int m0 = (w & 3) * 32, n0 = (w >> 2) * 64;
    const uint32_t aRowOff = (uint32_t)(m0 + (lane & 15)) * SKPB + (lane >> 4) * 16;
    const uint32_t bRowW = sb + SA_WH + (uint32_t)(n0 + (lane & 7)) * SKPB +
                           ((lane >> 3) & 1) * 16;
    char* gyc = (char*)g_y;

    build_w_bf16(smc, W1, tid);

    const int t0 = blockIdx.x;
    float4 xreg[16];
#pragma unroll
    for (int rr = 0; rr < 16; rr++) {
        int row = t0 * 128 + w16 + rr;
        xreg[rr] = *(const float4*)(x + (size_t)(row < N_PTS ? row : 0) * D + c0);
    }
#pragma unroll
    for (int rr = 0; rr < 16; rr++) {
        uint2 hi, lo; split4(xreg[rr], hi, lo);
        uint32_t off = (uint32_t)(w16 + rr) * SKPB + c0 * 2;
        *(uint2*)(smc + off) = hi;
        *(uint2*)(smc + TILE_B + off) = lo;
    }
    {
        int tn = t0 + NSM;
#pragma unroll
        for (int rr = 0; rr < 16; rr++) {
            int row = tn * 128 + w16 + rr;
            xreg[rr] = *(const float4*)(x + (size_t)(row < N_PTS ? row : 0) * D + c0);
        }
    }
    __syncthreads();

    int p = 0;
    for (int t = t0; t < TILES_A; t += NSM, p ^= 1) {
        const uint32_t abuf = sb + p * BUF_SZ;
        char* cb = smc + (p ^ 1) * BUF_SZ;
        const int t2 = t + 2 * NSM;

        float d[2][8][4];
#pragma unroll
        for (int mt = 0; mt < 2; mt++)
#pragma unroll
            for (int nt = 0; nt < 8; nt++)
#pragma unroll
                for (int j = 0; j < 4; j++) d[mt][nt][j] = 0.f;

#pragma unroll
        for (int ks = 0; ks < 8; ks++) {
            mma_kstep64(abuf, aRowOff, bRowW, ks, d);
            const int rr = 2 * ks;
#pragma unroll
            for (int q = 0; q < 2; q++) {
                uint2 hi, lo; split4(xreg[rr + q], hi, lo);
                uint32_t off = (uint32_t)(w16 + rr + q) * SKPB + c0 * 2;
                *(uint2*)(cb + off) = hi;
                *(uint2*)(cb + TILE_B + off) = lo;
                int row = t2 * 128 + w16 + rr + q;
                xreg[rr + q] =
                    *(const float4*)(x + (size_t)(row < N_PTS ? row : 0) * D + c0);
            }
        }

        const int g = lane >> 2, tt2 = 2 * (lane & 3);
        const int base = t * 128;
#pragma unroll
        for (int mt = 0; mt < 2; mt++) {
            int row0 = base + m0 + mt * 16 + g;
#pragma unroll
            for (int nt = 0; nt < 8; nt++) {
                int col = n0 + nt * 8 + tt2;
                if (row0 < N_PTS)
                    *(uint32_t*)(gyc + ((size_t)row0 * D + col) * 2) =
                        cvt_f16x2(d[mt][nt][1], d[mt][nt][0]);
                if (row0 + 8 < N_PTS)
                    *(uint32_t*)(gyc + ((size_t)(row0 + 8) * D + col) * 2) =
                        cvt_f16x2(d[mt][nt][3], d[mt][nt][2]);
            }
        }
        __syncthreads();
    }
}

// =====================================================================
// Kernel B (R10 structure: 512 thr, 16 warps m32xn32, plain fp16),
// g_y gathered as fp16
// =====================================================================
__device__ __forceinline__ void build_w_f16(char* smc, const float* W, int tid) {
    for (int i = tid; i < 128 * 128; i += 512) {
        int k = i >> 7, n = i & 127;
        *(__half*)(smc + B_WH + n * SKPB + k * 2) = __float2half_rn(W[i]);
    }
}
__device__ __forceinline__ void prefetch_ix(uint32_t sb, const int* idx,
                                            const float* xyz, int tile, int slot,
                                            int tid) {
    if (tile >= TILES_BK) tile = TILES_BK - 1;
    if (tid < 32)
        cp16(sb + B_IDX + slot * 512 + tid * 16, idx + (size_t)tile * 128 + tid * 4);
    else if (tid < 128)
        cp16(sb + B_XYZ + slot * 1536 + (tid - 32) * 16,
             xyz + (size_t)tile * 384 + (tid - 32) * 4);
}

// one k-step: 4 LDSM + 8 HMMA for a warp's m32 x n32 slab
__device__ __forceinline__ void mma_kstep32(uint32_t abuf, uint32_t aRowOff,
                                            uint32_t bRow4, int ks, float d[2][4][4]) {
    const uint32_t kb = ks * 32;
    uint32_t a[2][4];
#pragma unroll
    for (int mt = 0; mt < 2; mt++)
        ldsm_x4(abuf + aRowOff + (uint32_t)mt * 16 * SKPB + kb, a[mt]);
    uint32_t b[8];
    ldsm_x4(bRow4 + kb, b);
    ldsm_x4(bRow4 + 16 * SKPB + kb, b + 4);
#pragma unroll
    for (int mt = 0; mt < 2; mt++)
#pragma unroll
        for (int nt = 0; nt < 4; nt++)
            mma_f16(d[mt][nt], a[mt], &b[(nt >> 1) * 4 + (nt & 1) * 2]);
}

__global__ void __launch_bounds__(512, 1)
gemm2_pool_kernel(const int*   __restrict__ idx,
                  const float* __restrict__ xyz,
                  const float* __restrict__ W1,
                  const float* __restrict__ b1,
                  const float* __restrict__ W2,
                  const float* __restrict__ b2,
                  float* __restrict__ out) {
    extern __shared__ char smc[];
    const uint32_t sb = smem_u32(smc);
    const int tid = threadIdx.x, w = tid >> 5, lane = tid & 31;
    const int w8 = w * 8, c0 = lane * 4;
    const int m0 = (w & 3) * 32, n0 = (w >> 2) * 32;
    const uint32_t aRowOff = (uint32_t)(m0 + (lane & 15)) * SKPB + (lane >> 4) * 16;
    const uint32_t bRow4 = sb + B_WH +
        (uint32_t)(n0 + (lane & 7) + ((lane >> 4) & 1) * 8) * SKPB +
        ((lane >> 3) & 1) * 16;
    const char* gyc = (const char*)g_y;
    const uint32_t lane8 = lane * 8;
    float* b2s = (float*)(smc + B_B2);

    build_w_f16(smc, W2, tid);
    if (tid < 128) b2s[tid] = b2[tid];

    const float4 wA = *(const float4*)(W1 + 128 * 128 + c0);
    const float4 wB = *(const float4*)(W1 + 129 * 128 + c0);
    const float4 wC = *(const float4*)(W1 + 130 * 128 + c0);
    const float4 bb = *(const float4*)(b1 + c0);

    const int t0 = blockIdx.x;
    prefetch_ix(sb, idx, xyz, t0, 0, tid);
    prefetch_ix(sb, idx, xyz, t0 + NSM, 1, tid);
    prefetch_ix(sb, idx, xyz, t0 + 2 * NSM, 2, tid);
    cp_commit();
    cp_wait0();
    __syncthreads();

    // prologue: gather+convert tile t0 -> buf0 (8 rows per warp)
    {
        const int* idxs = (const int*)(smc + B_IDX);
        const float* xz = (const float*)(smc + B_XYZ);
#pragma unroll
        for (int rr = 0; rr < 8; rr++) {
            int r = w8 + rr;
            int id = idxs[r];
            uint2 yv = *(const uint2*)(gyc + (size_t)id * 256 + lane8);
            float2 f01 = __half22float2(*(__half2*)&yv.x);
            float2 f23 = __half22float2(*(__half2*)&yv.y);
            float4 v = make_float4(f01.x, f01.y, f23.x, f23.y);
            float px = xz[r * 3], py = xz[r * 3 + 1], pz = xz[r * 3 + 2];
            v.x += px * wA.x + py * wB.x + pz * wC.x + bb.x;
            v.y += px * wA.y + py * wB.y + pz * wC.y + bb.y;
            v.z += px * wA.z + py * wB.z + pz * wC.z + bb.z;
            v.w += px * wA.w + py * wB.w + pz * wC.w + bb.w;
            v = leaky4(v);
            uint32_t off = (uint32_t)r * SKPB + c0 * 2;
            *(uint2*)(smc + off) =
                make_uint2(cvt_f16x2(v.y, v.x), cvt_f16x2(v.w, v.z));
        }
    }
    __syncthreads();

    uint2 yring[4];
    int p = 0, i = 0;
    for (int t = t0; t < TILES_BK; t += NSM, i++, p ^= 1) {
        const int* idx1 = (const int*)(smc + B_IDX + ((i + 1) & 3) * 512);
        const float* xz1 = (const float*)(smc + B_XYZ + ((i + 1) & 3) * 1536);
        const uint32_t abuf = sb + p * TILE_B;
        char* cb = smc + (p ^ 1) * TILE_B;

        float d[2][4][4];
#pragma unroll
        for (int mt = 0; mt < 2; mt++)
#pragma unroll
            for (int nt = 0; nt < 4; nt++)
#pragma unroll
                for (int j = 0; j < 4; j++) d[mt][nt][j] = 0.f;

#pragma unroll
        for (int ks = 0; ks < 8; ks++) {
            mma_kstep32(abuf, aRowOff, bRow4, ks, d);
            // convert rows gathered 2 steps ago BEFORE regathering same slots
            if (ks >= 2 && ks < 6) {
                const int rr = 2 * (ks - 2);
#pragma unroll
                for (int q = 0; q < 2; q++) {
                    int r = w8 + rr + q;
                    uint2 yv = yring[(rr + q) & 3];
                    float2 f01 = __half22float2(*(__half2*)&yv.x);
                    float2 f23 = __half22float2(*(__half2*)&yv.y);
                    float4 v = make_float4(f01.x, f01.y, f23.x, f23.y);
                    float px = xz1[r * 3], py = xz1[r * 3 + 1], pz = xz1[r * 3 + 2];
                    v.x += px * wA.x + py * wB.x + pz * wC.x + bb.x;
                    v.y += px * wA.y + py * wB.y + pz * wC.y + bb.y;
                    v.z += px * wA.z + py * wB.z + pz * wC.z + bb.z;
                    v.w += px * wA.w + py * wB.w + pz * wC.w + bb.w;
                    v = leaky4(v);
                    uint32_t off = (uint32_t)r * SKPB + c0 * 2;
                    *(uint2*)(cb + off) =
                        make_uint2(cvt_f16x2(v.y, v.x), cvt_f16x2(v.w, v.z));
                }
            }
            if (ks < 4) {
                const int rg = 2 * ks;
#pragma unroll
                for (int q = 0; q < 2; q++) {
                    int id = idx1[w8 + rg + q];
                    yring[(rg + q) & 3] =
                        *(const uint2*)(gyc + (size_t)id * 256 + lane8);
                }
            }
        }

        cp_wait0();
        prefetch_ix(sb, idx, xyz, t + 3 * NSM, (i + 3) & 3, tid);
        cp_commit();

        // epilogue: maxpool over 8 rows, +b2, store
        const long rowbase = (long)t * 128;
        const int tt2 = 2 * (lane & 3);
#pragma unroll
        for (int mt = 0; mt < 2; mt++) {
            long p0 = (rowbase + m0 + mt * 16) >> 3;
            long p1 = p0 + 1;
#pragma unroll
            for (int nt = 0; nt < 4; nt++) {
                float v0 = d[mt][nt][0], v1 = d[mt][nt][1];
                float v2 = d[mt][nt][2], v3 = d[mt][nt][3];
#pragma unroll
                for (int s = 4; s < 32; s <<= 1) {
                    v0 = fmaxf(v0, __shfl_xor_sync(0xffffffffu, v0, s));
                    v1 = fmaxf(v1, __shfl_xor_sync(0xffffffffu, v1, s));
                    v2 = fmaxf(v2, __shfl_xor_sync(0xffffffffu, v2, s));
                    v3 = fmaxf(v3, __shfl_xor_sync(0xffffffffu, v3, s));
                }
                if (lane < 4) {
                    int col = n0 + nt * 8 + tt2;
                    float bx = b2s[col], by = b2s[col + 1];
                    *(float2*)(out + (size_t)p0 * D + col) = make_float2(v0 + bx, v1 + by);
                    *(float2*)(out + (size_t)p1 * D + col) = make_float2(v2 + bx, v3 + by);
                }
            }
        }
        __syncthreads();
    }
}

// =====================================================================
extern "C" void kernel_launch(void* const* d_in, const int* in_sizes, int n_in,
                              void* d_out, int out_size) {
    const float* x   = (const float*)d_in[0];
    const int*   idx = (const int*)d_in[1];
    const float* xyz = (const float*)d_in[2];
    const float* W1  = (const float*)d_in[3];
    const float* b1  = (const float*)d_in[4];
    const float* W2  = (const float*)d_in[5];
    const float* b2  = (const float*)d_in[6];
    float* out = (float*)d_out;

    cudaFuncSetAttribute(gemm1_kernel,
                         cudaFuncAttributeMaxDynamicSharedMemorySize, SA_TOT);
    cudaFuncSetAttribute(gemm2_pool_kernel,
                         cudaFuncAttributeMaxDynamicSharedMemorySize, B_TOT);

    gemm1_kernel<<<NSM, 256, SA_TOT>>>(x, W1);
    gemm2_pool_kernel<<<NSM, 512, B_TOT>>>(idx, xyz, W1, b1, W2, b2, out);
}

// round 15
// speedup vs baseline: 1.4815x; 1.0950x over previous
#include <cuda_runtime.h>
#include <cuda_bf16.h>
#include <cuda_fp16.h>
#include <cstdint>

#define N_PTS 100000
#define D 128
#define NSM 148
#define SKPB 272               // 16b row stride in bytes (136 elems)
#define TILE_B 34816           // 128 * 272
#define TILES_A 782
#define TILES_BK 6250          // 800000 / 128

// kernel A smem layout (plain fp16): XH[2] | W
#define SA_W    69632
#define SA_TOT  104448

// kernel B smem layout (R10/R14: TILE_M=128, plain fp16, 512 thr)
#define B_WH    69632                  // after 2 single-image A buffers
#define B_IDX   104448                 // 4 * 512
#define B_XYZ   106496                 // 4 * 1536
#define B_B2    112640                 // 512
#define B_TOT   113152

__device__ __half g_y[(size_t)N_PTS * D];

// ---------------- helpers ----------------
__device__ __forceinline__ uint32_t smem_u32(const void* p) {
    uint32_t a;
    asm("{ .reg .u64 t; cvta.to.shared.u64 t, %1; cvt.u32.u64 %0, t; }"
        : "=r"(a) : "l"(p));
    return a;
}
__device__ __forceinline__ uint32_t cvt_f16x2(float hi, float lo) {
    uint32_t r;
    asm("cvt.rn.f16x2.f32 %0, %1, %2;" : "=r"(r) : "f"(hi), "f"(lo));
    return r;
}
__device__ __forceinline__ void cp16(uint32_t dst, const void* src) {
    asm volatile("cp.async.cg.shared.global [%0], [%1], 16;"
                 :: "r"(dst), "l"(src) : "memory");
}
__device__ __forceinline__ void cp_commit() {
    asm volatile("cp.async.commit_group;" ::: "memory");
}
__device__ __forceinline__ void cp_wait0() {
    asm volatile("cp.async.wait_group 0;" ::: "memory");
}
__device__ __forceinline__ void ldsm_x4(uint32_t addr, uint32_t* r) {
    asm volatile("ldmatrix.sync.aligned.m8n8.x4.shared.b16 {%0,%1,%2,%3}, [%4];"
                 : "=r"(r[0]), "=r"(r[1]), "=r"(r[2]), "=r"(r[3]) : "r"(addr));
}
__device__ __forceinline__ void mma_f16(float* d, const uint32_t* a, const uint32_t* b) {
    asm volatile(
        "mma.sync.aligned.m16n8k16.row.col.f32.f16.f16.f32 "
        "{%0,%1,%2,%3}, {%4,%5,%6,%7}, {%8,%9}, {%0,%1,%2,%3};"
        : "+f"(d[0]), "+f"(d[1]), "+f"(d[2]), "+f"(d[3])
        : "r"(a[0]), "r"(a[1]), "r"(a[2]), "r"(a[3]), "r"(b[0]), "r"(b[1]));
}

// half2 layer-1 params
struct L1P {
    __half2 wA01, wA23, wB01, wB23, wC01, wC23, bb01, bb23;
};
// convert one gathered fp16 y row to activation (half2 math)
__device__ __forceinline__ uint2 conv_h2(uint2 yv, float px, float py, float pz,
                                         const L1P& P) {
    __half2 px2 = __float2half2_rn(px);
    __half2 py2 = __float2half2_rn(py);
    __half2 pz2 = __float2half2_rn(pz);
    __half2 v01 = __hadd2(*(__half2*)&yv.x, P.bb01);
    __half2 v23 = __hadd2(*(__half2*)&yv.y, P.bb23);
    v01 = __hfma2(px2, P.wA01, v01);  v23 = __hfma2(px2, P.wA23, v23);
    v01 = __hfma2(py2, P.wB01, v01);  v23 = __hfma2(py2, P.wB23, v23);
    v01 = __hfma2(pz2, P.wC01, v01);  v23 = __hfma2(pz2, P.wC23, v23);
    const __half2 slope = __float2half2_rn(0.01f);
    v01 = __hmax2(v01, __hmul2(slope, v01));
    v23 = __hmax2(v23, __hmul2(slope, v23));
    uint2 r;
    r.x = *(uint32_t*)&v01;
    r.y = *(uint32_t*)&v23;
    return r;
}

// =====================================================================
// Kernel A (persistent, pipelined, 256 thr, plain fp16): y = x @ W1a
// =====================================================================
__global__ void __launch_bounds__(256, 1)
gemm1_kernel(const float* __restrict__ x, const float* __restrict__ W1) {
    extern __shared__ char smc[];
    const uint32_t sb = smem_u32(smc);
    const int tid = threadIdx.x, w = tid >> 5, lane = tid & 31;
    const int w16 = w * 16, c0 = lane * 4;
    const int m0 = (w & 3) * 32, n0 = (w >> 2) * 64;
    const uint32_t aRowOff = (uint32_t)(m0 + (lane & 15)) * SKPB + (lane >> 4) * 16;
    const uint32_t bRow4 = sb + SA_W +
        (uint32_t)(n0 + (lane & 7) + ((lane >> 4) & 1) * 8) * SKPB +
        ((lane >> 3) & 1) * 16;
    char* gyc = (char*)g_y;

    // build W1a fp16 [n][k]
    for (int i = tid; i < 128 * 128; i += 256) {
        int k = i >> 7, n = i & 127;
        *(__half*)(smc + SA_W + n * SKPB + k * 2) = __float2half_rn(W1[i]);
    }

    const int t0 = blockIdx.x;
    float4 xreg[16];
#pragma unroll
    for (int rr = 0; rr < 16; rr++) {
        int row = t0 * 128 + w16 + rr;
        xreg[rr] = *(const float4*)(x + (size_t)(row < N_PTS ? row : 0) * D + c0);
    }
#pragma unroll
    for (int rr = 0; rr < 16; rr++) {
        uint32_t off = (uint32_t)(w16 + rr) * SKPB + c0 * 2;
        *(uint2*)(smc + off) = make_uint2(cvt_f16x2(xreg[rr].y, xreg[rr].x),
                                          cvt_f16x2(xreg[rr].w, xreg[rr].z));
    }
    {
        int tn = t0 + NSM;
#pragma unroll
        for (int rr = 0; rr < 16; rr++) {
            int row = tn * 128 + w16 + rr;
            xreg[rr] = *(const float4*)(x + (size_t)(row < N_PTS ? row : 0) * D + c0);
        }
    }
    __syncthreads();

    int p = 0;
    for (int t = t0; t < TILES_A; t += NSM, p ^= 1) {
        const uint32_t abuf = sb + p * TILE_B;
        char* cb = smc + (p ^ 1) * TILE_B;
        const int t2 = t + 2 * NSM;

        float d[2][8][4];
#pragma unroll
        for (int mt = 0; mt < 2; mt++)
#pragma unroll
            for (int nt = 0; nt < 8; nt++)
#pragma unroll
                for (int j = 0; j < 4; j++) d[mt][nt][j] = 0.f;

#pragma unroll
        for (int ks = 0; ks < 8; ks++) {
            const uint32_t kb = ks * 32;
            uint32_t a[2][4];
#pragma unroll
            for (int mt = 0; mt < 2; mt++)
                ldsm_x4(abuf + aRowOff + (uint32_t)mt * 16 * SKPB + kb, a[mt]);
            uint32_t b[16];
#pragma unroll
            for (int g = 0; g < 4; g++)
                ldsm_x4(bRow4 + (uint32_t)g * 16 * SKPB + kb, b + g * 4);
#pragma unroll
            for (int mt = 0; mt < 2; mt++)
#pragma unroll
                for (int nt = 0; nt < 8; nt++)
                    mma_f16(d[mt][nt], a[mt], &b[(nt >> 1) * 4 + (nt & 1) * 2]);

            // interleaved: convert 2 rows of t+NSM, load 2 rows of t+2NSM
            const int rr = 2 * ks;
#pragma unroll
            for (int q = 0; q < 2; q++) {
                float4 v = xreg[rr + q];
                uint32_t off = (uint32_t)(w16 + rr + q) * SKPB + c0 * 2;
                *(uint2*)(cb + off) =
                    make_uint2(cvt_f16x2(v.y, v.x), cvt_f16x2(v.w, v.z));
                int row = t2 * 128 + w16 + rr + q;
                xreg[rr + q] =
                    *(const float4*)(x + (size_t)(row < N_PTS ? row : 0) * D + c0);
            }
        }

        const int g = lane >> 2, tt2 = 2 * (lane & 3);
        const int base = t * 128;
#pragma unroll
        for (int mt = 0; mt < 2; mt++) {
            int row0 = base + m0 + mt * 16 + g;
#pragma unroll
            for (int nt = 0; nt < 8; nt++) {
                int col = n0 + nt * 8 + tt2;
                if (row0 < N_PTS)
                    *(uint32_t*)(gyc + ((size_t)row0 * D + col) * 2) =
                        cvt_f16x2(d[mt][nt][1], d[mt][nt][0]);
                if (row0 + 8 < N_PTS)
                    *(uint32_t*)(gyc + ((size_t)(row0 + 8) * D + col) * 2) =
                        cvt_f16x2(d[mt][nt][3], d[mt][nt][2]);
            }
        }
        __syncthreads();
    }
}

// =====================================================================
// Kernel B (R14 structure: 512 thr, 16 warps m32xn32, plain fp16),
// convert math in half2
// =====================================================================
__device__ __forceinline__ void prefetch_ix(uint32_t sb, const int* idx,
                                            const float* xyz, int tile, int slot,
                                            int tid) {
    if (tile >= TILES_BK) tile = TILES_BK - 1;
    if (tid < 32)
        cp16(sb + B_IDX + slot * 512 + tid * 16, idx + (size_t)tile * 128 + tid * 4);
    else if (tid < 128)
        cp16(sb + B_XYZ + slot * 1536 + (tid - 32) * 16,
             xyz + (size_t)tile * 384 + (tid - 32) * 4);
}

// one k-step: 4 LDSM + 8 HMMA for a warp's m32 x n32 slab
__device__ __forceinline__ void mma_kstep32(uint32_t abuf, uint32_t aRowOff,
                                            uint32_t bRow4, int ks, float d[2][4][4]) {
    const uint32_t kb = ks * 32;
    uint32_t a[2][4];
#pragma unroll
    for (int mt = 0; mt < 2; mt++)
        ldsm_x4(abuf + aRowOff + (uint32_t)mt * 16 * SKPB + kb, a[mt]);
    uint32_t b[8];
    ldsm_x4(bRow4 + kb, b);
    ldsm_x4(bRow4 + 16 * SKPB + kb, b + 4);
#pragma unroll
    for (int mt = 0; mt < 2; mt++)
#pragma unroll
        for (int nt = 0; nt < 4; nt++)
            mma_f16(d[mt][nt], a[mt], &b[(nt >> 1) * 4 + (nt & 1) * 2]);
}

__global__ void __launch_bounds__(512, 1)
gemm2_pool_kernel(const int*   __restrict__ idx,
                  const float* __restrict__ xyz,
                  const float* __restrict__ W1,
                  const float* __restrict__ b1,
                  const float* __restrict__ W2,
                  const float* __restrict__ b2,
                  float* __restrict__ out) {
    extern __shared__ char smc[];
    const uint32_t sb = smem_u32(smc);
    const int tid = threadIdx.x, w = tid >> 5, lane = tid & 31;
    const int w8 = w * 8, c0 = lane * 4;
    const int m0 = (w & 3) * 32, n0 = (w >> 2) * 32;
    const uint32_t aRowOff = (uint32_t)(m0 + (lane & 15)) * SKPB + (lane >> 4) * 16;
    const uint32_t bRow4 = sb + B_WH +
        (uint32_t)(n0 + (lane & 7) + ((lane >> 4) & 1) * 8) * SKPB +
        ((lane >> 3) & 1) * 16;
    const char* gyc = (const char*)g_y;
    const uint32_t lane8 = lane * 8;
    float* b2s = (float*)(smc + B_B2);

    // build W2 fp16 [n][k]
    for (int i = tid; i < 128 * 128; i += 512) {
        int k = i >> 7, n = i & 127;
        *(__half*)(smc + B_WH + n * SKPB + k * 2) = __float2half_rn(W2[i]);
    }
    if (tid < 128) b2s[tid] = b2[tid];

    // layer-1 params as half2 (loop-invariant)
    L1P P;
    {
        float4 a = *(const float4*)(W1 + 128 * 128 + c0);
        float4 b = *(const float4*)(W1 + 129 * 128 + c0);
        float4 c = *(const float4*)(W1 + 130 * 128 + c0);
        float4 e = *(const float4*)(b1 + c0);
        P.wA01 = __floats2half2_rn(a.x, a.y); P.wA23 = __floats2half2_rn(a.z, a.w);
        P.wB01 = __floats2half2_rn(b.x, b.y); P.wB23 = __floats2half2_rn(b.z, b.w);
        P.wC01 = __floats2half2_rn(c.x, c.y); P.wC23 = __floats2half2_rn(c.z, c.w);
        P.bb01 = __floats2half2_rn(e.x, e.y); P.bb23 = __floats2half2_rn(e.z, e.w);
    }

    const int t0 = blockIdx.x;
    prefetch_ix(sb, idx, xyz, t0, 0, tid);
    prefetch_ix(sb, idx, xyz, t0 + NSM, 1, tid);
    prefetch_ix(sb, idx, xyz, t0 + 2 * NSM, 2, tid);
    cp_commit();
    cp_wait0();
    __syncthreads();

    // prologue: gather+convert tile t0 -> buf0 (8 rows per warp)
    {
        const int* idxs = (const int*)(smc + B_IDX);
        const float* xz = (const float*)(smc + B_XYZ);
#pragma unroll
        for (int rr = 0; rr < 8; rr++) {
            int r = w8 + rr;
            int id = idxs[r];
            uint2 yv = *(const uint2*)(gyc + (size_t)id * 256 + lane8);
            *(uint2*)(smc + (uint32_t)r * SKPB + c0 * 2) =
                conv_h2(yv, xz[r * 3], xz[r * 3 + 1], xz[r * 3 + 2], P);
        }
    }
    __syncthreads();

    uint2 yring[4];
    int p = 0, i = 0;
    for (int t = t0; t < TILES_BK; t += NSM, i++, p ^= 1) {
        const int* idx1 = (const int*)(smc + B_IDX + ((i + 1) & 3) * 512);
        const float* xz1 = (const float*)(smc + B_XYZ + ((i + 1) & 3) * 1536);
        const uint32_t abuf = sb + p * TILE_B;
        char* cb = smc + (p ^ 1) * TILE_B;

        float d[2][4][4];
#pragma unroll
        for (int mt = 0; mt < 2; mt++)
#pragma unroll
            for (int nt = 0; nt < 4; nt++)
#pragma unroll
                for (int j = 0; j < 4; j++) d[mt][nt][j] = 0.f;

#pragma unroll
        for (int ks = 0; ks < 8; ks++) {
            mma_kstep32(abuf, aRowOff, bRow4, ks, d);
            // convert rows gathered 2 steps ago BEFORE regathering same slots
            if (ks >= 2 && ks < 6) {
                const int rr = 2 * (ks - 2);
#pragma unroll
                for (int q = 0; q < 2; q++) {
                    int r = w8 + rr + q;
                    *(uint2*)(cb + (uint32_t)r * SKPB + c0 * 2) =
                        conv_h2(yring[(rr + q) & 3],
                                xz1[r * 3], xz1[r * 3 + 1], xz1[r * 3 + 2], P);
                }
            }
            if (ks < 4) {
                const int rg = 2 * ks;
#pragma unroll
                for (int q = 0; q < 2; q++) {
                    int id = idx1[w8 + rg + q];
                    yring[(rg + q) & 3] =
                        *(const uint2*)(gyc + (size_t)id * 256 + lane8);
                }
            }
        }

        cp_wait0();
        prefetch_ix(sb, idx, xyz, t + 3 * NSM, (i + 3) & 3, tid);
        cp_commit();

        // epilogue: maxpool over 8 rows, +b2, store
        const long rowbase = (long)t * 128;
        const int tt2 = 2 * (lane & 3);
#pragma unroll
        for (int mt = 0; mt < 2; mt++) {
            long p0 = (rowbase + m0 + mt * 16) >> 3;
            long p1 = p0 + 1;
#pragma unroll
            for (int nt = 0; nt < 4; nt++) {
                float v0 = d[mt][nt][0], v1 = d[mt][nt][1];
                float v2 = d[mt][nt][2], v3 = d[mt][nt][3];
#pragma unroll
                for (int s = 4; s < 32; s <<= 1) {
                    v0 = fmaxf(v0, __shfl_xor_sync(0xffffffffu, v0, s));
                    v1 = fmaxf(v1, __shfl_xor_sync(0xffffffffu, v1, s));
                    v2 = fmaxf(v2, __shfl_xor_sync(0xffffffffu, v2, s));
                    v3 = fmaxf(v3, __shfl_xor_sync(0xffffffffu, v3, s));
                }
                if (lane < 4) {
                    int col = n0 + nt * 8 + tt2;
                    float bx = b2s[col], by = b2s[col + 1];
                    *(float2*)(out + (size_t)p0 * D + col) = make_float2(v0 + bx, v1 + by);
                    *(float2*)(out + (size_t)p1 * D + col) = make_float2(v2 + bx, v3 + by);
                }
            }
        }
        __syncthreads();
    }
}

// =====================================================================
extern "C" void kernel_launch(void* const* d_in, const int* in_sizes, int n_in,
                              void* d_out, int out_size) {
    const float* x   = (const float*)d_in[0];
    const int*   idx = (const int*)d_in[1];
    const float* xyz = (const float*)d_in[2];
    const float* W1  = (const float*)d_in[3];
    const float* b1  = (const float*)d_in[4];
    const float* W2  = (const float*)d_in[5];
    const float* b2  = (const float*)d_in[6];
    float* out = (float*)d_out;

    cudaFuncSetAttribute(gemm1_kernel,
                         cudaFuncAttributeMaxDynamicSharedMemorySize, SA_TOT);
    cudaFuncSetAttribute(gemm2_pool_kernel,
                         cudaFuncAttributeMaxDynamicSharedMemorySize, B_TOT);

    gemm1_kernel<<<NSM, 256, SA_TOT>>>(x, W1);
    gemm2_pool_kernel<<<NSM, 512, B_TOT>>>(idx, xyz, W1, b1, W2, b2, out);
}

// round 17
// speedup vs baseline: 1.5487x; 1.0454x over previous
#include <cuda_runtime.h>
#include <cuda_bf16.h>
#include <cuda_fp16.h>
#include <cstdint>

#define N_PTS 100000
#define D 128
#define NSM 148
#define NGRP 296               // 2 tile pipelines per CTA
#define SKPB 272               // 16b row stride in bytes (136 elems)
#define TILE_B 34816           // 128 * 272
#define TILES_A 782
#define TILES_BK 6250          // 800000 / 128

// kernel A smem layout (plain fp16): X[2] | W
#define SA_W    69632
#define SA_TOT  104448

// kernel B smem layout: A buffers [4 x TILE_B] | W | b2 | idx | xyz
#define B_W     139264
#define B_B2    174080
#define B_IDX   174592                 // 2 groups x 4 slots x 512
#define B_XYZ   178688                 // 2 groups x 4 slots x 1536
#define B_TOT   190976

__device__ __half g_y[(size_t)N_PTS * D];

// ---------------- helpers ----------------
__device__ __forceinline__ uint32_t smem_u32(const void* p) {
    uint32_t a;
    asm("{ .reg .u64 t; cvta.to.shared.u64 t, %1; cvt.u32.u64 %0, t; }"
        : "=r"(a) : "l"(p));
    return a;
}
__device__ __forceinline__ uint32_t cvt_f16x2(float hi, float lo) {
    uint32_t r;
    asm("cvt.rn.f16x2.f32 %0, %1, %2;" : "=r"(r) : "f"(hi), "f"(lo));
    return r;
}
__device__ __forceinline__ void cp16(uint32_t dst, const void* src) {
    asm volatile("cp.async.cg.shared.global [%0], [%1], 16;"
                 :: "r"(dst), "l"(src) : "memory");
}
__device__ __forceinline__ void cp_commit() {
    asm volatile("cp.async.commit_group;" ::: "memory");
}
__device__ __forceinline__ void cp_wait0() {
    asm volatile("cp.async.wait_group 0;" ::: "memory");
}
__device__ __forceinline__ void bar_g(int g) {
    asm volatile("bar.sync %0, 256;" :: "r"(1 + g) : "memory");
}
__device__ __forceinline__ void ldsm_x4(uint32_t addr, uint32_t* r) {
    asm volatile("ldmatrix.sync.aligned.m8n8.x4.shared.b16 {%0,%1,%2,%3}, [%4];"
                 : "=r"(r[0]), "=r"(r[1]), "=r"(r[2]), "=r"(r[3]) : "r"(addr));
}
__device__ __forceinline__ void mma_f16(float* d, const uint32_t* a, const uint32_t* b) {
    asm volatile(
        "mma.sync.aligned.m16n8k16.row.col.f32.f16.f16.f32 "
        "{%0,%1,%2,%3}, {%4,%5,%6,%7}, {%8,%9}, {%0,%1,%2,%3};"
        : "+f"(d[0]), "+f"(d[1]), "+f"(d[2]), "+f"(d[3])
        : "r"(a[0]), "r"(a[1]), "r"(a[2]), "r"(a[3]), "r"(b[0]), "r"(b[1]));
}

// half2 layer-1 params
struct L1P {
    __half2 wA01, wA23, wB01, wB23, wC01, wC23, bb01, bb23;
};
__device__ __forceinline__ uint2 conv_h2(uint2 yv, float px, float py, float pz,
                                         const L1P& P) {
    __half2 px2 = __float2half2_rn(px);
    __half2 py2 = __float2half2_rn(py);
    __half2 pz2 = __float2half2_rn(pz);
    __half2 v01 = __hadd2(*(__half2*)&yv.x, P.bb01);
    __half2 v23 = __hadd2(*(__half2*)&yv.y, P.bb23);
    v01 = __hfma2(px2, P.wA01, v01);  v23 = __hfma2(px2, P.wA23, v23);
    v01 = __hfma2(py2, P.wB01, v01);  v23 = __hfma2(py2, P.wB23, v23);
    v01 = __hfma2(pz2, P.wC01, v01);  v23 = __hfma2(pz2, P.wC23, v23);
    const __half2 slope = __float2half2_rn(0.01f);
    v01 = __hmax2(v01, __hmul2(slope, v01));
    v23 = __hmax2(v23, __hmul2(slope, v23));
    uint2 r;
    r.x = *(uint32_t*)&v01;
    r.y = *(uint32_t*)&v23;
    return r;
}

// =====================================================================
// Kernel A (persistent, pipelined, 256 thr, plain fp16): y = x @ W1a
// (unchanged from R15)
// =====================================================================
__global__ void __launch_bounds__(256, 1)
gemm1_kernel(const float* __restrict__ x, const float* __restrict__ W1) {
    extern __shared__ char smc[];
    const uint32_t sb = smem_u32(smc);
    const int tid = threadIdx.x, w = tid >> 5, lane = tid & 31;
    const int w16 = w * 16, c0 = lane * 4;
    const int m0 = (w & 3) * 32, n0 = (w >> 2) * 64;
    const uint32_t aRowOff = (uint32_t)(m0 + (lane & 15)) * SKPB + (lane >> 4) * 16;
    const uint32_t bRow4 = sb + SA_W +
        (uint32_t)(n0 + (lane & 7) + ((lane >> 4) & 1) * 8) * SKPB +
        ((lane >> 3) & 1) * 16;
    char* gyc = (char*)g_y;

    for (int i = tid; i < 128 * 128; i += 256) {
        int k = i >> 7, n = i & 127;
        *(__half*)(smc + SA_W + n * SKPB + k * 2) = __float2half_rn(W1[i]);
    }

    const int t0 = blockIdx.x;
    float4 xreg[16];
#pragma unroll
    for (int rr = 0; rr < 16; rr++) {
        int row = t0 * 128 + w16 + rr;
        xreg[rr] = *(const float4*)(x + (size_t)(row < N_PTS ? row : 0) * D + c0);
    }
#pragma unroll
    for (int rr = 0; rr < 16; rr++) {
        uint32_t off = (uint32_t)(w16 + rr) * SKPB + c0 * 2;
        *(uint2*)(smc + off) = make_uint2(cvt_f16x2(xreg[rr].y, xreg[rr].x),
                                          cvt_f16x2(xreg[rr].w, xreg[rr].z));
    }
    {
        int tn = t0 + NSM;
#pragma unroll
        for (int rr = 0; rr < 16; rr++) {
            int row = tn * 128 + w16 + rr;
            xreg[rr] = *(const float4*)(x + (size_t)(row < N_PTS ? row : 0) * D + c0);
        }
    }
    __syncthreads();

    int p = 0;
    for (int t = t0; t < TILES_A; t += NSM, p ^= 1) {
        const uint32_t abuf = sb + p * TILE_B;
        char* cb = smc + (p ^ 1) * TILE_B;
        const int t2 = t + 2 * NSM;

        float d[2][8][4];
#pragma unroll
        for (int mt = 0; mt < 2; mt++)
#pragma unroll
            for (int nt = 0; nt < 8; nt++)
#pragma unroll
                for (int j = 0; j < 4; j++) d[mt][nt][j] = 0.f;

#pragma unroll
        for (int ks = 0; ks < 8; ks++) {
            const uint32_t kb = ks * 32;
            uint32_t a[2][4];
#pragma unroll
            for (int mt = 0; mt < 2; mt++)
                ldsm_x4(abuf + aRowOff + (uint32_t)mt * 16 * SKPB + kb, a[mt]);
            uint32_t b[16];
#pragma unroll
            for (int g = 0; g < 4; g++)
                ldsm_x4(bRow4 + (uint32_t)g * 16 * SKPB + kb, b + g * 4);
#pragma unroll
            for (int mt = 0; mt < 2; mt++)
#pragma unroll
                for (int nt = 0; nt < 8; nt++)
                    mma_f16(d[mt][nt], a[mt], &b[(nt >> 1) * 4 + (nt & 1) * 2]);

            const int rr = 2 * ks;
#pragma unroll
            for (int q = 0; q < 2; q++) {
                float4 v = xreg[rr + q];
                uint32_t off = (uint32_t)(w16 + rr + q) * SKPB + c0 * 2;
                *(uint2*)(cb + off) =
                    make_uint2(cvt_f16x2(v.y, v.x), cvt_f16x2(v.w, v.z));
                int row = t2 * 128 + w16 + rr + q;
                xreg[rr + q] =
                    *(const float4*)(x + (size_t)(row < N_PTS ? row : 0) * D + c0);
            }
        }

        const int g = lane >> 2, tt2 = 2 * (lane & 3);
        const int base = t * 128;
#pragma unroll
        for (int mt = 0; mt < 2; mt++) {
            int row0 = base + m0 + mt * 16 + g;
#pragma unroll
            for (int nt = 0; nt < 8; nt++) {
                int col = n0 + nt * 8 + tt2;
                if (row0 < N_PTS)
                    *(uint32_t*)(gyc + ((size_t)row0 * D + col) * 2) =
                        cvt_f16x2(d[mt][nt][1], d[mt][nt][0]);
                if (row0 + 8 < N_PTS)
                    *(uint32_t*)(gyc + ((size_t)(row0 + 8) * D + col) * 2) =
                        cvt_f16x2(d[mt][nt][3], d[mt][nt][2]);
            }
        }
        __syncthreads();
    }
}

// =====================================================================
// Kernel B: 512 thr = 2 independent 8-warp tile pipelines (m64xn32
// slabs), plain fp16, half2 convert, per-group named barriers
// =====================================================================
__device__ __forceinline__ void prefetch_ix_g(uint32_t sb, const int* idx,
                                              const float* xyz, int tile,
                                              int slot, int ptid, int g) {
    if (tile >= TILES_BK) tile = TILES_BK - 1;
    if (ptid < 32)
        cp16(sb + B_IDX + g * 2048 + slot * 512 + ptid * 16,
             idx + (size_t)tile * 128 + ptid * 4);
    else if (ptid < 128)
        cp16(sb + B_XYZ + g * 6144 + slot * 1536 + (ptid - 32) * 16,
             xyz + (size_t)tile * 384 + (ptid - 32) * 4);
}

__global__ void __launch_bounds__(512, 1)
gemm2_pool_kernel(const int*   __restrict__ idx,
                  const float* __restrict__ xyz,
                  const float* __restrict__ W1,
                  const float* __restrict__ b1,
                  const float* __restrict__ W2,
                  const float* __restrict__ b2,
                  float* __restrict__ out) {
    extern __shared__ char smc[];
    const uint32_t sb = smem_u32(smc);
    const int tid = threadIdx.x, w = tid >> 5, lane = tid & 31;
    const int g = w >> 3, wg = w & 7;
    const int ptid = tid & 255;
    const int w16 = wg * 16, c0 = lane * 4;
    const int m0 = (wg & 1) * 64, n0 = (wg >> 1) * 32;
    char* gbuf = smc + (uint32_t)g * 2 * TILE_B;         // generic ptr (stores)
    const uint32_t gA = sb + (uint32_t)g * 2 * TILE_B;   // shared addr (LDSM)
    const uint32_t aRowOff = (uint32_t)(m0 + (lane & 15)) * SKPB + (lane >> 4) * 16;
    const uint32_t bRow4 = sb + B_W +
        (uint32_t)(n0 + (lane & 7) + ((lane >> 4) & 1) * 8) * SKPB +
        ((lane >> 3) & 1) * 16;
    const char* gyc = (const char*)g_y;
    const uint32_t lane8 = lane * 8;
    float* b2s = (float*)(smc + B_B2);
    const int* idxR = (const int*)(smc + B_IDX + g * 2048);
    const float* xyzR = (const float*)(smc + B_XYZ + g * 6144);

    // build W2 fp16 [n][k] (all threads)
    for (int i = tid; i < 128 * 128; i += 512) {
        int k = i >> 7, n = i & 127;
        *(__half*)(smc + B_W + n * SKPB + k * 2) = __float2half_rn(W2[i]);
    }
    if (tid < 128) b2s[tid] = b2[tid];

    // layer-1 params as half2
    L1P P;
    {
        float4 a = *(const float4*)(W1 + 128 * 128 + c0);
        float4 b = *(const float4*)(W1 + 129 * 128 + c0);
        float4 c = *(const float4*)(W1 + 130 * 128 + c0);
        float4 e = *(const float4*)(b1 + c0);
        P.wA01 = __floats2half2_rn(a.x, a.y); P.wA23 = __floats2half2_rn(a.z, a.w);
        P.wB01 = __floats2half2_rn(b.x, b.y); P.wB23 = __floats2half2_rn(b.z, b.w);
        P.wC01 = __floats2half2_rn(c.x, c.y); P.wC23 = __floats2half2_rn(c.z, c.w);
        P.bb01 = __floats2half2_rn(e.x, e.y); P.bb23 = __floats2half2_rn(e.z, e.w);
    }

    const int G = blockIdx.x * 2 + g;          // group id: 0..295
    prefetch_ix_g(sb, idx, xyz, G, 0, ptid, g);
    prefetch_ix_g(sb, idx, xyz, G + NGRP, 1, ptid, g);
    prefetch_ix_g(sb, idx, xyz, G + 2 * NGRP, 2, ptid, g);
    cp_commit();
    __syncthreads();            // W2 image + b2 visible to everyone (once)
    cp_wait0();
    bar_g(g);

    // prologue: gather+convert tile G -> group's buf0 (16 rows per warp)
    {
#pragma unroll 4
        for (int rr = 0; rr < 16; rr++) {
            int r = w16 + rr;
            int id = idxR[r];
            uint2 yv = *(const uint2*)(gyc + (size_t)id * 256 + lane8);
            *(uint2*)(gbuf + (uint32_t)r * SKPB + c0 * 2) =
                conv_h2(yv, xyzR[r * 3], xyzR[r * 3 + 1], xyzR[r * 3 + 2], P);
        }
    }
    bar_g(g);

    uint2 yring[4];
    int p = 0, i = 0;
    for (int t = G; t < TILES_BK; t += NGRP, i++, p ^= 1) {
        const int* idx1 = idxR + ((i + 1) & 3) * 128;
        const float* xz1 = xyzR + ((i + 1) & 3) * 384;
        const uint32_t abuf = gA + p * TILE_B;
        char* cb = gbuf + (p ^ 1) * TILE_B;

        float d[4][4][4];
#pragma unroll
        for (int mt = 0; mt < 4; mt++)
#pragma unroll
            for (int nt = 0; nt < 4; nt++)
#pragma unroll
                for (int j = 0; j < 4; j++) d[mt][nt][j] = 0.f;

#pragma unroll
        for (int ks = 0; ks < 8; ks++) {
            const uint32_t kb = ks * 32;
            uint32_t b[8];
            ldsm_x4(bRow4 + kb, b);
            ldsm_x4(bRow4 + 16 * SKPB + kb, b + 4);
#pragma unroll
            for (int mt = 0; mt < 4; mt++) {
                uint32_t a[4];
                ldsm_x4(abuf + aRowOff + (uint32_t)mt * 16 * SKPB + kb, a);
#pragma unroll
                for (int nt = 0; nt < 4; nt++)
                    mma_f16(d[mt][nt], a, &b[(nt >> 1) * 4 + (nt & 1) * 2]);
            }

            // convert rows gathered 2 steps ago BEFORE regathering same slots
            if (ks >= 2) {
                const int rr = 2 * (ks - 2);
#pragma unroll
                for (int q = 0; q < 2; q++) {
                    int r = w16 + rr + q;
                    *(uint2*)(cb + (uint32_t)r * SKPB + c0 * 2) =
                        conv_h2(yring[(rr + q) & 3],
                                xz1[r * 3], xz1[r * 3 + 1], xz1[r * 3 + 2], P);
                }
            }
            const int rg = 2 * ks;
#pragma unroll
            for (int q = 0; q < 2; q++) {
                int id = idx1[w16 + rg + q];
                yring[(rg + q) & 3] =
                    *(const uint2*)(gyc + (size_t)id * 256 + lane8);
            }
        }
        // tail converts: rows 12..15
#pragma unroll
        for (int rr = 12; rr < 16; rr++) {
            int r = w16 + rr;
            *(uint2*)(cb + (uint32_t)r * SKPB + c0 * 2) =
                conv_h2(yring[rr & 3],
                        xz1[r * 3], xz1[r * 3 + 1], xz1[r * 3 + 2], P);
        }

        cp_wait0();
        prefetch_ix_g(sb, idx, xyz, t + 3 * NGRP, (i + 3) & 3, ptid, g);
        cp_commit();

        // epilogue: maxpool over 8 rows, +b2, store
        const long rowbase = (long)t * 128;
        const int tt2 = 2 * (lane & 3);
#pragma unroll
        for (int mt = 0; mt < 4; mt++) {
            long p0 = (rowbase + m0 + mt * 16) >> 3;
            long p1 = p0 + 1;
#pragma unroll
            for (int nt = 0; nt < 4; nt++) {
                float v0 = d[mt][nt][0], v1 = d[mt][nt][1];
                float v2 = d[mt][nt][2], v3 = d[mt][nt][3];
#pragma unroll
                for (int s = 4; s < 32; s <<= 1) {
                    v0 = fmaxf(v0, __shfl_xor_sync(0xffffffffu, v0, s));
                    v1 = fmaxf(v1, __shfl_xor_sync(0xffffffffu, v1, s));
                    v2 = fmaxf(v2, __shfl_xor_sync(0xffffffffu, v2, s));
                    v3 = fmaxf(v3, __shfl_xor_sync(0xffffffffu, v3, s));
                }
                if (lane < 4) {
                    int col = n0 + nt * 8 + tt2;
                    float bx = b2s[col], by = b2s[col + 1];
                    *(float2*)(out + (size_t)p0 * D + col) = make_float2(v0 + bx, v1 + by);
                    *(float2*)(out + (size_t)p1 * D + col) = make_float2(v2 + bx, v3 + by);
                }
            }
        }
        bar_g(g);
    }
}

// =====================================================================
extern "C" void kernel_launch(void* const* d_in, const int* in_sizes, int n_in,
                              void* d_out, int out_size) {
    const float* x   = (const float*)d_in[0];
    const int*   idx = (const int*)d_in[1];
    const float* xyz = (const float*)d_in[2];
    const float* W1  = (const float*)d_in[3];
    const float* b1  = (const float*)d_in[4];
    const float* W2  = (const float*)d_in[5];
    const float* b2  = (const float*)d_in[6];
    float* out = (float*)d_out;

    cudaFuncSetAttribute(gemm1_kernel,
                         cudaFuncAttributeMaxDynamicSharedMemorySize, SA_TOT);
    cudaFuncSetAttribute(gemm2_pool_kernel,
                         cudaFuncAttributeMaxDynamicSharedMemorySize, B_TOT);

    gemm1_kernel<<<NSM, 256, SA_TOT>>>(x, W1);
    gemm2_pool_kernel<<<NSM, 512, B_TOT>>>(idx, xyz, W1, b1, W2, b2, out);
}